// round 6
// baseline (speedup 1.0000x reference)
#include <cuda_runtime.h>

// VectorQuantizer: single-pass warp bf16 mma.sync (m16n8k16) with running
// margin threshold -> candidate queue -> exact fp32 re-score.
// inputs [32,64,64,64] f32 NCHW, weight [512,64] f32.
// out[0..N*D) = fl(x + fl(q-x)) NCHW; out[N*D..) = 1.25*mean((q-x)^2).

#define KCODES  512
#define DDIM    64
#define HWSZ    4096
#define NTOT    131072
#define TILE_M  256
#define NTILES  (NTOT / TILE_M)   // 512
#define NTHREADS 256
#define QCAP    8192

typedef unsigned int u32;
typedef unsigned long long u64;
typedef unsigned short u16;

__device__ float g_partials[NTILES];

// ---- smem layout (bytes) ----
#define BSTRIDE  520                               // u32 per c2-row; bank-conflict-free
#define OFF_B    0                                 // bf16x2 codebook [32][520]u32 = 66560
#define OFF_A    (32 * BSTRIDE * 4)                // fp32 x-tile [256][65] = 66560
#define ASTRIDE  65
#define OFF_SWN  (OFF_A + TILE_M * ASTRIDE * 4)    // 512 f32 = 2048
#define OFF_SX   (OFF_SWN + 2048)                  // 256 f32 = 1024
#define OFF_KEY  (OFF_SX + 1024)                   // 256 u64 = 2048
#define OFF_QCNT (OFF_KEY + 2048)                  // 16
#define OFF_OVF  (OFF_QCNT + 16)                   // 256
#define OFF_QUE  (OFF_OVF + 256)                   // QCAP*4 = 32768
#define SMEM_TOTAL (OFF_QUE + QCAP * 4)            // 171280 B

// ---- scalar helpers ----
__device__ __forceinline__ u32 bf16x2_pack(float lo, float hi) {
    // PTX packs first src into UPPER half: d = {hi:cvt(a), lo:cvt(b)}
    u32 r; asm("cvt.rn.bf16x2.f32 %0, %1, %2;" : "=r"(r) : "f"(hi), "f"(lo)); return r;
}
__device__ __forceinline__ u64 ffma2(u64 a, u64 b, u64 c) {
    u64 d; asm("fma.rn.f32x2 %0, %1, %2, %3;" : "=l"(d) : "l"(a), "l"(b), "l"(c)); return d;
}
__device__ __forceinline__ u64 fadd2(u64 a, u64 b) {
    u64 d; asm("add.rn.f32x2 %0, %1, %2;" : "=l"(d) : "l"(a), "l"(b)); return d;
}
__device__ __forceinline__ u64 pack2(float lo, float hi) {
    u64 d; asm("mov.b64 %0, {%1, %2};" : "=l"(d) : "f"(lo), "f"(hi)); return d;
}
__device__ __forceinline__ void unpack2(u64 v, float& lo, float& hi) {
    asm("mov.b64 {%0, %1}, %2;" : "=f"(lo), "=f"(hi) : "l"(v));
}

#define MMAB(c, a, b0, b1)                                                      \
    asm volatile("mma.sync.aligned.m16n8k16.row.col.f32.bf16.bf16.f32 "         \
                 "{%0,%1,%2,%3}, {%4,%5,%6,%7}, {%8,%9}, {%0,%1,%2,%3};"        \
                 : "+f"((c)[0]), "+f"((c)[1]), "+f"((c)[2]), "+f"((c)[3])       \
                 : "r"((a)[0]), "r"((a)[1]), "r"((a)[2]), "r"((a)[3]),          \
                   "r"(b0), "r"(b1))

// exact fp32 score, bit-identical to the round-2 passing pipeline.
__device__ __forceinline__ float exact_d(const float* __restrict__ xrow,
                                         const float* __restrict__ wrow,
                                         float sx, float swn_k) {
    u64 a0 = 0ull, a1 = 0ull, a2 = 0ull, a3 = 0ull;
    #pragma unroll
    for (int j = 0; j < DDIM / 2; j += 4) {
        u64 x0 = pack2(xrow[2*(j+0)], xrow[2*(j+0)+1]);
        u64 x1 = pack2(xrow[2*(j+1)], xrow[2*(j+1)+1]);
        u64 x2 = pack2(xrow[2*(j+2)], xrow[2*(j+2)+1]);
        u64 x3 = pack2(xrow[2*(j+3)], xrow[2*(j+3)+1]);
        u64 w0 = pack2(wrow[2*(j+0)], wrow[2*(j+0)+1]);
        u64 w1 = pack2(wrow[2*(j+1)], wrow[2*(j+1)+1]);
        u64 w2 = pack2(wrow[2*(j+2)], wrow[2*(j+2)+1]);
        u64 w3 = pack2(wrow[2*(j+3)], wrow[2*(j+3)+1]);
        a0 = ffma2(x0, w0, a0);
        a1 = ffma2(x1, w1, a1);
        a2 = ffma2(x2, w2, a2);
        a3 = ffma2(x3, w3, a3);
    }
    a0 = fadd2(a0, a1);
    a2 = fadd2(a2, a3);
    a0 = fadd2(a0, a2);
    float lo, hi;
    unpack2(a0, lo, hi);
    float dot = __fadd_rn(lo, hi);
    float t = __fadd_rn(sx, swn_k);
    return __fsub_rn(t, __fmul_rn(2.0f, dot));
}

extern __shared__ char smem[];

__global__ void __launch_bounds__(NTHREADS, 1)
vq_mma_kernel(const float* __restrict__ input,
              const float* __restrict__ weight,
              float* __restrict__ out)
{
    u32*   Bp    = (u32*)(smem + OFF_B);
    float* A32   = (float*)(smem + OFF_A);
    float* SWN   = (float*)(smem + OFF_SWN);
    float* SX    = (float*)(smem + OFF_SX);
    u64*   KEY   = (u64*)(smem + OFF_KEY);
    u32*   QCNT  = (u32*)(smem + OFF_QCNT);
    unsigned char* SOVF = (unsigned char*)(smem + OFF_OVF);
    u32*   QUE   = (u32*)(smem + OFF_QUE);

    const int tid = threadIdx.x;
    const int b   = blockIdx.x >> 4;
    const int hw0 = (blockIdx.x & 15) * TILE_M;
    const float* inb = input + (size_t)b * DDIM * HWSZ + hw0 + tid;

    KEY[tid] = ~0ull;
    SOVF[tid] = 0;
    if (tid == 0) *QCNT = 0;

    // ---- stage A (fp32) + exact sequential sx ----
    float sx = 0.f;
    {
        float* arow = A32 + tid * ASTRIDE;
        #pragma unroll
        for (int c = 0; c < DDIM; c++) {
            float v = inb[(size_t)c * HWSZ];
            arow[c] = v;
            sx = __fadd_rn(sx, __fmul_rn(v, v));
        }
        SX[tid] = sx;
    }

    // ---- stage B (bf16 pairs, [c2][n] padded) + exact sequential norms ----
    #pragma unroll
    for (int r = 0; r < 2; r++) {
        const int n = tid + r * NTHREADS;
        const float4* wr = (const float4*)(weight + (size_t)n * DDIM);
        float s = 0.f;
        #pragma unroll
        for (int c4 = 0; c4 < DDIM / 4; c4++) {
            float4 wv = wr[c4];
            s = __fadd_rn(s, __fmul_rn(wv.x, wv.x));
            s = __fadd_rn(s, __fmul_rn(wv.y, wv.y));
            s = __fadd_rn(s, __fmul_rn(wv.z, wv.z));
            s = __fadd_rn(s, __fmul_rn(wv.w, wv.w));
            Bp[(c4 * 2 + 0) * BSTRIDE + n] = bf16x2_pack(wv.x, wv.y);
            Bp[(c4 * 2 + 1) * BSTRIDE + n] = bf16x2_pack(wv.z, wv.w);
        }
        SWN[n] = s;
    }
    __syncthreads();

    // ---- A fragments (bf16) ----
    const int lane  = tid & 31;
    const int g     = lane >> 2;
    const int tq    = lane & 3;
    const int rbase = (tid >> 5) * 32;

    u32 afr[2][4][4];     // [mt][ks4][reg]
    #pragma unroll
    for (int mt = 0; mt < 2; mt++) {
        const float* r0 = A32 + (rbase + mt * 16 + g) * ASTRIDE;
        const float* r1 = r0 + 8 * ASTRIDE;
        #pragma unroll
        for (int ks = 0; ks < 4; ks++) {
            const int k0 = ks * 16 + 2 * tq;
            afr[mt][ks][0] = bf16x2_pack(r0[k0],     r0[k0 + 1]);
            afr[mt][ks][1] = bf16x2_pack(r1[k0],     r1[k0 + 1]);
            afr[mt][ks][2] = bf16x2_pack(r0[k0 + 8], r0[k0 + 9]);
            afr[mt][ks][3] = bf16x2_pack(r1[k0 + 8], r1[k0 + 9]);
        }
    }

    // slot s = mt*2 + (e>>1) ; row = rbase + mt*16 + (s&1)*8 + g
    float mrg[4], bmin[4];
    #pragma unroll
    for (int s = 0; s < 4; s++) {
        int row = rbase + (s >> 1) * 16 + (s & 1) * 8 + g;
        mrg[s]  = fmaf(sqrtf(SX[row]), 4e-4f, 6e-5f);
        bmin[s] = 3.4e38f;
    }

    // ======== single pass: MMA + running-threshold collect ========
    const unsigned FULL = 0xffffffffu;
    #pragma unroll 1
    for (int n2 = 0; n2 < 32; n2++) {
        const int nb = n2 * 16;
        float acc[2][2][4];
        #pragma unroll
        for (int i = 0; i < 2; i++)
            #pragma unroll
            for (int j = 0; j < 2; j++)
                #pragma unroll
                for (int e = 0; e < 4; e++) acc[i][j][e] = 0.f;

        #pragma unroll
        for (int ks = 0; ks < 4; ks++) {
            const u32* p0 = Bp + (ks * 8 + tq) * BSTRIDE + nb + g;
            const u32* p1 = p0 + 4 * BSTRIDE;
            u32 b0a = p0[0], b0b = p0[8];
            u32 b1a = p1[0], b1b = p1[8];
            MMAB(acc[0][0], afr[0][ks], b0a, b1a);
            MMAB(acc[0][1], afr[0][ks], b0b, b1b);
            MMAB(acc[1][0], afr[1][ks], b0a, b1a);
            MMAB(acc[1][1], afr[1][ks], b0b, b1b);
        }

        float swnc[2][2];
        swnc[0][0] = SWN[nb + tq * 2];
        swnc[0][1] = SWN[nb + tq * 2 + 1];
        swnc[1][0] = SWN[nb + 8 + tq * 2];
        swnc[1][1] = SWN[nb + 8 + tq * 2 + 1];

        #pragma unroll
        for (int mt = 0; mt < 2; mt++)
        #pragma unroll
        for (int nn = 0; nn < 2; nn++)
        #pragma unroll
        for (int e = 0; e < 4; e++) {
            const int s   = mt * 2 + (e >> 1);
            const int col = nb + nn * 8 + tq * 2 + (e & 1);
            const int row = rbase + mt * 16 + (e >> 1) * 8 + g;
            float dt = fmaf(-2.f, acc[mt][nn][e], swnc[nn][e & 1]);
            bmin[s] = fminf(bmin[s], dt);
            bool take = (dt <= bmin[s] + mrg[s]);
            unsigned m = __ballot_sync(FULL, take);
            if (m) {
                int leader = __ffs(m) - 1;
                u32 base = 0;
                if (lane == leader) base = atomicAdd(QCNT, (u32)__popc(m));
                base = __shfl_sync(FULL, base, leader);
                if (take) {
                    u32 pos = base + (u32)__popc(m & ((1u << lane) - 1u));
                    if (pos < QCAP) QUE[pos] = ((u32)row << 16) | (u32)col;
                    else SOVF[row] = 1;
                }
            }
        }

        // periodically share min across the quad to tighten threshold
        if ((n2 & 3) == 3) {
            #pragma unroll
            for (int s = 0; s < 4; s++) {
                float bm = bmin[s];
                bm = fminf(bm, __shfl_xor_sync(FULL, bm, 1));
                bm = fminf(bm, __shfl_xor_sync(FULL, bm, 2));
                bmin[s] = bm;
            }
        }
    }
    __syncthreads();

    // ======== exact rescore of queue (cooperative) ========
    {
        int qn = *QCNT;
        if (qn > QCAP) qn = QCAP;
        for (int i = tid; i < qn; i += NTHREADS) {
            u32 e = QUE[i];
            int row = e >> 16;
            int k   = e & 0xffff;
            float d = exact_d(A32 + row * ASTRIDE, weight + (size_t)k * DDIM,
                              SX[row], SWN[k]);
            u64 key = ((u64)__float_as_uint(d) << 16) | (u64)k;
            atomicMin(&KEY[row], key);
        }
    }
    __syncthreads();

    // ======== epilogue: gather, straight-through out, loss ========
    {
        const float* xrow = A32 + tid * ASTRIDE;
        int bidx;
        if (SOVF[tid]) {   // overflow fallback: full exact scan (rare)
            float best = 3.4e38f; bidx = 0;
            for (int k = 0; k < KCODES; k++) {
                float d = exact_d(xrow, weight + (size_t)k * DDIM, sx, SWN[k]);
                if (d < best) { best = d; bidx = k; }
            }
        } else {
            bidx = (int)(KEY[tid] & 0xffffull);
        }

        const float* qrow = weight + (size_t)bidx * DDIM;
        float* outp = out + (size_t)b * DDIM * HWSZ + hw0 + tid;
        float lloss = 0.f;
        #pragma unroll
        for (int c = 0; c < DDIM; c++) {
            float q = qrow[c];
            float x = xrow[c];
            float e = __fsub_rn(q, x);
            outp[(size_t)c * HWSZ] = __fadd_rn(x, e);
            lloss = fmaf(e, e, lloss);
        }

        __syncthreads();
        SX[tid] = lloss;
        __syncthreads();
        #pragma unroll
        for (int st = NTHREADS / 2; st > 0; st >>= 1) {
            if (tid < st) SX[tid] += SX[tid + st];
            __syncthreads();
        }
        if (tid == 0) g_partials[blockIdx.x] = SX[0];
    }
}

__global__ void loss_kernel(float* __restrict__ out, int out_size)
{
    __shared__ float red[256];
    const int tid = threadIdx.x;
    float s = 0.f;
    for (int i = tid; i < NTILES; i += 256) s += g_partials[i];
    red[tid] = s;
    __syncthreads();
    #pragma unroll
    for (int st = 128; st > 0; st >>= 1) {
        if (tid < st) red[tid] += red[tid + st];
        __syncthreads();
    }
    if (tid == 0) {
        float loss = red[0] * 1.25f / (float)((long long)NTOT * DDIM);
        for (long long i = (long long)NTOT * DDIM; i < out_size; i++)
            out[i] = loss;
    }
}

extern "C" void kernel_launch(void* const* d_in, const int* in_sizes, int n_in,
                              void* d_out, int out_size)
{
    const float* input  = (const float*)d_in[0];
    const float* weight = (const float*)d_in[1];
    float* out = (float*)d_out;

    cudaFuncSetAttribute(vq_mma_kernel, cudaFuncAttributeMaxDynamicSharedMemorySize, SMEM_TOTAL);
    vq_mma_kernel<<<NTILES, NTHREADS, SMEM_TOTAL>>>(input, weight, out);
    loss_kernel<<<1, 256>>>(out, out_size);
}

// round 7
// speedup vs baseline: 2.5379x; 2.5379x over previous
#include <cuda_runtime.h>

// VectorQuantizer: two-pass warp bf16 mma.sync (m16n8k16), 16 warps/CTA with
// codebook split across warp pairs, + exact fp32 re-score of queued candidates.
// inputs [32,64,64,64] f32 NCHW, weight [512,64] f32.
// out[0..N*D) = fl(x + fl(q-x)) NCHW; out[N*D..) = 1.25*mean((q-x)^2).

#define KCODES  512
#define DDIM    64
#define HWSZ    4096
#define NTOT    131072
#define TILE_M  256
#define NTILES  (NTOT / TILE_M)   // 512
#define NTHREADS 512
#define QCAP    4096

typedef unsigned int u32;
typedef unsigned long long u64;
typedef unsigned short u16;

__device__ float g_partials[NTILES];

// ---- smem layout (bytes) ----
#define BSTRIDE  520                               // u32 per c2-row; conflict-free
#define OFF_B    0                                 // bf16x2 codebook [32][520] = 66560
#define OFF_A    66560                             // fp32 x-tile [256][65] = 66560
#define ASTRIDE  65
#define OFF_SWN  (OFF_A + 66560)                   // 512 f32 = 2048
#define OFF_SX   (OFF_SWN + 2048)                  // 256 f32 = 1024
#define OFF_KEY  (OFF_SX + 1024)                   // 256 u64 = 2048
#define OFF_BMH  (OFF_KEY + 2048)                  // 512 f32 (row x half) = 2048
#define OFF_QCNT (OFF_BMH + 2048)                  // 16
#define OFF_OVF  (OFF_QCNT + 16)                   // 256
#define OFF_QUE  (OFF_OVF + 256)                   // QCAP*4 = 16384
#define SMEM_TOTAL (OFF_QUE + QCAP * 4)            // 156944 B

// ---- scalar helpers ----
__device__ __forceinline__ u32 bf16x2_pack(float lo, float hi) {
    u32 r; asm("cvt.rn.bf16x2.f32 %0, %1, %2;" : "=r"(r) : "f"(hi), "f"(lo)); return r;
}
__device__ __forceinline__ u64 ffma2(u64 a, u64 b, u64 c) {
    u64 d; asm("fma.rn.f32x2 %0, %1, %2, %3;" : "=l"(d) : "l"(a), "l"(b), "l"(c)); return d;
}
__device__ __forceinline__ u64 fadd2(u64 a, u64 b) {
    u64 d; asm("add.rn.f32x2 %0, %1, %2;" : "=l"(d) : "l"(a), "l"(b)); return d;
}
__device__ __forceinline__ u64 pack2(float lo, float hi) {
    u64 d; asm("mov.b64 %0, {%1, %2};" : "=l"(d) : "f"(lo), "f"(hi)); return d;
}
__device__ __forceinline__ void unpack2(u64 v, float& lo, float& hi) {
    asm("mov.b64 {%0, %1}, %2;" : "=f"(lo), "=f"(hi) : "l"(v));
}

#define MMAB(c, a, b0, b1)                                                      \
    asm volatile("mma.sync.aligned.m16n8k16.row.col.f32.bf16.bf16.f32 "         \
                 "{%0,%1,%2,%3}, {%4,%5,%6,%7}, {%8,%9}, {%0,%1,%2,%3};"        \
                 : "+f"((c)[0]), "+f"((c)[1]), "+f"((c)[2]), "+f"((c)[3])       \
                 : "r"((a)[0]), "r"((a)[1]), "r"((a)[2]), "r"((a)[3]),          \
                   "r"(b0), "r"(b1))

// exact fp32 score, bit-identical to the round-2 passing pipeline.
__device__ __forceinline__ float exact_d(const float* __restrict__ xrow,
                                         const float* __restrict__ wrow,
                                         float sx, float swn_k) {
    u64 a0 = 0ull, a1 = 0ull, a2 = 0ull, a3 = 0ull;
    #pragma unroll
    for (int j = 0; j < DDIM / 2; j += 4) {
        u64 x0 = pack2(xrow[2*(j+0)], xrow[2*(j+0)+1]);
        u64 x1 = pack2(xrow[2*(j+1)], xrow[2*(j+1)+1]);
        u64 x2 = pack2(xrow[2*(j+2)], xrow[2*(j+2)+1]);
        u64 x3 = pack2(xrow[2*(j+3)], xrow[2*(j+3)+1]);
        u64 w0 = pack2(wrow[2*(j+0)], wrow[2*(j+0)+1]);
        u64 w1 = pack2(wrow[2*(j+1)], wrow[2*(j+1)+1]);
        u64 w2 = pack2(wrow[2*(j+2)], wrow[2*(j+2)+1]);
        u64 w3 = pack2(wrow[2*(j+3)], wrow[2*(j+3)+1]);
        a0 = ffma2(x0, w0, a0);
        a1 = ffma2(x1, w1, a1);
        a2 = ffma2(x2, w2, a2);
        a3 = ffma2(x3, w3, a3);
    }
    a0 = fadd2(a0, a1);
    a2 = fadd2(a2, a3);
    a0 = fadd2(a0, a2);
    float lo, hi;
    unpack2(a0, lo, hi);
    float dot = __fadd_rn(lo, hi);
    float t = __fadd_rn(sx, swn_k);
    return __fsub_rn(t, __fmul_rn(2.0f, dot));
}

extern __shared__ char smem[];

__global__ void __launch_bounds__(NTHREADS, 1)
vq_mma_kernel(const float* __restrict__ input,
              const float* __restrict__ weight,
              float* __restrict__ out)
{
    u32*   Bp    = (u32*)(smem + OFF_B);
    float* A32   = (float*)(smem + OFF_A);
    float* SWN   = (float*)(smem + OFF_SWN);
    float* SX    = (float*)(smem + OFF_SX);
    u64*   KEY   = (u64*)(smem + OFF_KEY);
    float* BMH   = (float*)(smem + OFF_BMH);
    u32*   QCNT  = (u32*)(smem + OFF_QCNT);
    unsigned char* SOVF = (unsigned char*)(smem + OFF_OVF);
    u32*   QUE   = (u32*)(smem + OFF_QUE);

    const int tid = threadIdx.x;
    const int b   = blockIdx.x >> 4;
    const int hw0 = (blockIdx.x & 15) * TILE_M;

    // ---- init ----
    if (tid < 256) { KEY[tid] = ~0ull; SOVF[tid] = 0; }
    if (tid == 0) *QCNT = 0;

    // ---- stage A (fp32, rows 0..255 by threads 0..255) + exact sequential sx ----
    if (tid < 256) {
        const float* inb = input + (size_t)b * DDIM * HWSZ + hw0 + tid;
        float* arow = A32 + tid * ASTRIDE;
        float sx = 0.f;
        #pragma unroll
        for (int c = 0; c < DDIM; c++) {
            float v = inb[(size_t)c * HWSZ];
            arow[c] = v;
            sx = __fadd_rn(sx, __fmul_rn(v, v));
        }
        SX[tid] = sx;
    }

    // ---- stage B (bf16 pairs, [c2][n]) + exact sequential norms (n = tid) ----
    {
        const int n = tid;
        const float4* wr = (const float4*)(weight + (size_t)n * DDIM);
        float s = 0.f;
        #pragma unroll
        for (int c4 = 0; c4 < DDIM / 4; c4++) {
            float4 wv = wr[c4];
            s = __fadd_rn(s, __fmul_rn(wv.x, wv.x));
            s = __fadd_rn(s, __fmul_rn(wv.y, wv.y));
            s = __fadd_rn(s, __fmul_rn(wv.z, wv.z));
            s = __fadd_rn(s, __fmul_rn(wv.w, wv.w));
            Bp[(c4 * 2 + 0) * BSTRIDE + n] = bf16x2_pack(wv.x, wv.y);
            Bp[(c4 * 2 + 1) * BSTRIDE + n] = bf16x2_pack(wv.z, wv.w);
        }
        SWN[n] = s;
    }
    __syncthreads();

    // ---- warp roles: 8 row-groups x 2 code-halves ----
    const int lane  = tid & 31;
    const int g     = lane >> 2;
    const int tq    = lane & 3;
    const int w     = tid >> 5;
    const int rbase = (w >> 1) * 32;      // 32 rows per group
    const int h     = w & 1;              // code half
    const int nb0   = h * 256;

    // ---- A fragments (bf16; mapping validated in r6) ----
    u32 afr[2][4][4];
    #pragma unroll
    for (int mt = 0; mt < 2; mt++) {
        const float* r0 = A32 + (rbase + mt * 16 + g) * ASTRIDE;
        const float* r1 = r0 + 8 * ASTRIDE;
        #pragma unroll
        for (int ks = 0; ks < 4; ks++) {
            const int k0 = ks * 16 + 2 * tq;
            afr[mt][ks][0] = bf16x2_pack(r0[k0],     r0[k0 + 1]);
            afr[mt][ks][1] = bf16x2_pack(r1[k0],     r1[k0 + 1]);
            afr[mt][ks][2] = bf16x2_pack(r0[k0 + 8], r0[k0 + 9]);
            afr[mt][ks][3] = bf16x2_pack(r1[k0 + 8], r1[k0 + 9]);
        }
    }

    // slot s = mt*2 + (e>>1) ; row = rbase + (s>>1)*16 + (s&1)*8 + g
    float bmin[4] = {3.4e38f, 3.4e38f, 3.4e38f, 3.4e38f};

    // ================= PASS 1: min only (branchless) =================
    #pragma unroll 1
    for (int n2 = 0; n2 < 16; n2++) {
        const int nb = nb0 + n2 * 16;
        float acc[2][2][4];
        #pragma unroll
        for (int i = 0; i < 2; i++)
            #pragma unroll
            for (int j = 0; j < 2; j++)
                #pragma unroll
                for (int e = 0; e < 4; e++) acc[i][j][e] = 0.f;

        #pragma unroll
        for (int ks = 0; ks < 4; ks++) {
            const u32* p0 = Bp + (ks * 8 + tq) * BSTRIDE + nb + g;
            const u32* p1 = p0 + 4 * BSTRIDE;
            u32 b0a = p0[0], b0b = p0[8];
            u32 b1a = p1[0], b1b = p1[8];
            MMAB(acc[0][0], afr[0][ks], b0a, b1a);
            MMAB(acc[0][1], afr[0][ks], b0b, b1b);
            MMAB(acc[1][0], afr[1][ks], b0a, b1a);
            MMAB(acc[1][1], afr[1][ks], b0b, b1b);
        }

        float swnc[2][2];
        swnc[0][0] = SWN[nb + tq * 2];
        swnc[0][1] = SWN[nb + tq * 2 + 1];
        swnc[1][0] = SWN[nb + 8 + tq * 2];
        swnc[1][1] = SWN[nb + 8 + tq * 2 + 1];

        #pragma unroll
        for (int mt = 0; mt < 2; mt++)
        #pragma unroll
        for (int nn = 0; nn < 2; nn++)
        #pragma unroll
        for (int e = 0; e < 4; e++) {
            const int s = mt * 2 + (e >> 1);
            float dt = fmaf(-2.f, acc[mt][nn][e], swnc[nn][e & 1]);
            bmin[s] = fminf(bmin[s], dt);
        }
    }

    // quad-merge mins; publish per (row, half)
    const unsigned FULL = 0xffffffffu;
    #pragma unroll
    for (int s = 0; s < 4; s++) {
        float bm = bmin[s];
        bm = fminf(bm, __shfl_xor_sync(FULL, bm, 1));
        bm = fminf(bm, __shfl_xor_sync(FULL, bm, 2));
        if (tq == 0) {
            int row = rbase + (s >> 1) * 16 + (s & 1) * 8 + g;
            BMH[row * 2 + h] = bm;
        }
    }
    __syncthreads();

    // thresholds from merged halves
    float th[4];
    #pragma unroll
    for (int s = 0; s < 4; s++) {
        int row = rbase + (s >> 1) * 16 + (s & 1) * 8 + g;
        float bm = fminf(BMH[row * 2], BMH[row * 2 + 1]);
        float mrg = fmaf(sqrtf(SX[row]), 2.4414e-4f, 5e-5f);
        th[s] = bm + mrg;
    }

    // ================= PASS 2: recompute, collect into queue =================
    #pragma unroll 1
    for (int n2 = 0; n2 < 16; n2++) {
        const int nb = nb0 + n2 * 16;
        float acc[2][2][4];
        #pragma unroll
        for (int i = 0; i < 2; i++)
            #pragma unroll
            for (int j = 0; j < 2; j++)
                #pragma unroll
                for (int e = 0; e < 4; e++) acc[i][j][e] = 0.f;

        #pragma unroll
        for (int ks = 0; ks < 4; ks++) {
            const u32* p0 = Bp + (ks * 8 + tq) * BSTRIDE + nb + g;
            const u32* p1 = p0 + 4 * BSTRIDE;
            u32 b0a = p0[0], b0b = p0[8];
            u32 b1a = p1[0], b1b = p1[8];
            MMAB(acc[0][0], afr[0][ks], b0a, b1a);
            MMAB(acc[0][1], afr[0][ks], b0b, b1b);
            MMAB(acc[1][0], afr[1][ks], b0a, b1a);
            MMAB(acc[1][1], afr[1][ks], b0b, b1b);
        }

        float swnc[2][2];
        swnc[0][0] = SWN[nb + tq * 2];
        swnc[0][1] = SWN[nb + tq * 2 + 1];
        swnc[1][0] = SWN[nb + 8 + tq * 2];
        swnc[1][1] = SWN[nb + 8 + tq * 2 + 1];

        #pragma unroll
        for (int mt = 0; mt < 2; mt++)
        #pragma unroll
        for (int nn = 0; nn < 2; nn++)
        #pragma unroll
        for (int e = 0; e < 4; e++) {
            const int s   = mt * 2 + (e >> 1);
            const int col = nb + nn * 8 + tq * 2 + (e & 1);
            const int row = rbase + mt * 16 + (e >> 1) * 8 + g;
            float dt = fmaf(-2.f, acc[mt][nn][e], swnc[nn][e & 1]);
            bool take = (dt <= th[s]);
            unsigned m = __ballot_sync(FULL, take);
            if (m) {
                int leader = __ffs(m) - 1;
                u32 base = 0;
                if (lane == leader) base = atomicAdd(QCNT, (u32)__popc(m));
                base = __shfl_sync(FULL, base, leader);
                if (take) {
                    u32 pos = base + (u32)__popc(m & ((1u << lane) - 1u));
                    if (pos < QCAP) QUE[pos] = ((u32)row << 16) | (u32)col;
                    else SOVF[row] = 1;
                }
            }
        }
    }
    __syncthreads();

    // ================= exact rescore of queue (cooperative) =================
    {
        int qn = *QCNT;
        if (qn > QCAP) qn = QCAP;
        for (int i = tid; i < qn; i += NTHREADS) {
            u32 e = QUE[i];
            int row = e >> 16;
            int k   = e & 0xffff;
            float d = exact_d(A32 + row * ASTRIDE, weight + (size_t)k * DDIM,
                              SX[row], SWN[k]);
            u64 key = ((u64)__float_as_uint(d) << 16) | (u64)k;
            atomicMin(&KEY[row], key);
        }
    }
    __syncthreads();

    // ================= epilogue: 2 threads per row (c split) ===============
    {
        const int row = tid & 255;
        const int c0  = (tid >> 8) * 32;
        const float* xrow = A32 + row * ASTRIDE;
        const float sxr = SX[row];

        int bidx;
        if (SOVF[row]) {   // overflow fallback: full exact scan (never expected)
            float best = 3.4e38f; bidx = 0;
            for (int k = 0; k < KCODES; k++) {
                float d = exact_d(xrow, weight + (size_t)k * DDIM, sxr, SWN[k]);
                if (d < best) { best = d; bidx = k; }
            }
        } else {
            bidx = (int)(KEY[row] & 0xffffull);
        }

        const float* qrow = weight + (size_t)bidx * DDIM;
        float* outp = out + (size_t)b * DDIM * HWSZ + hw0 + row;
        float lloss = 0.f;
        #pragma unroll
        for (int c = c0; c < c0 + 32; c++) {
            float q = qrow[c];
            float x = xrow[c];
            float e = __fsub_rn(q, x);
            outp[(size_t)c * HWSZ] = __fadd_rn(x, e);
            lloss = fmaf(e, e, lloss);
        }

        // deterministic loss reduction (reuse Bp region, done with it)
        float* red = (float*)(smem + OFF_B);
        __syncthreads();
        red[tid] = lloss;
        __syncthreads();
        #pragma unroll
        for (int st = NTHREADS / 2; st > 0; st >>= 1) {
            if (tid < st) red[tid] += red[tid + st];
            __syncthreads();
        }
        if (tid == 0) g_partials[blockIdx.x] = red[0];
    }
}

__global__ void loss_kernel(float* __restrict__ out, int out_size)
{
    __shared__ float red[256];
    const int tid = threadIdx.x;
    float s = 0.f;
    for (int i = tid; i < NTILES; i += 256) s += g_partials[i];
    red[tid] = s;
    __syncthreads();
    #pragma unroll
    for (int st = 128; st > 0; st >>= 1) {
        if (tid < st) red[tid] += red[tid + st];
        __syncthreads();
    }
    if (tid == 0) {
        float loss = red[0] * 1.25f / (float)((long long)NTOT * DDIM);
        for (long long i = (long long)NTOT * DDIM; i < out_size; i++)
            out[i] = loss;
    }
}

extern "C" void kernel_launch(void* const* d_in, const int* in_sizes, int n_in,
                              void* d_out, int out_size)
{
    const float* input  = (const float*)d_in[0];
    const float* weight = (const float*)d_in[1];
    float* out = (float*)d_out;

    cudaFuncSetAttribute(vq_mma_kernel, cudaFuncAttributeMaxDynamicSharedMemorySize, SMEM_TOTAL);
    vq_mma_kernel<<<NTILES, NTHREADS, SMEM_TOTAL>>>(input, weight, out);
    loss_kernel<<<1, 256>>>(out, out_size);
}